// round 2
// baseline (speedup 1.0000x reference)
#include <cuda_runtime.h>
#include <math.h>

#define NN 8192
#define IN_F 128
#define OUT_F 64
#define ALPHA 0.2f

// Scratch (allocation-free rule: __device__ globals)
__device__ float g_h[NN * OUT_F];
__device__ float g_s1[NN];
__device__ float g_s2[NN];
__device__ float g_M;

// ---------------------------------------------------------------------------
// Kernel A: h = features @ W^T ; s1 = h @ a[:64] ; s2 = h @ a[64:]
// 16 rows per block, 1024 threads: thread (r = tid/64, f = tid%64)
// ---------------------------------------------------------------------------
__global__ __launch_bounds__(1024) void k_proj(const float* __restrict__ feat,
                                               const float* __restrict__ W,
                                               const float* __restrict__ a) {
    __shared__ float Ws[OUT_F][IN_F + 1];   // +1 pad: conflict-free
    __shared__ float Fs[16][IN_F];
    __shared__ float red1[32], red2[32];

    int tid = threadIdx.x;
    int i0  = blockIdx.x * 16;

    for (int t = tid; t < OUT_F * IN_F; t += 1024)
        Ws[t / IN_F][t % IN_F] = W[t];
    for (int t = tid; t < 16 * IN_F; t += 1024)
        Fs[t / IN_F][t % IN_F] = feat[(size_t)(i0 + t / IN_F) * IN_F + (t % IN_F)];
    __syncthreads();

    int f = tid & 63;
    int r = tid >> 6;
    float acc = 0.f;
#pragma unroll
    for (int k = 0; k < IN_F; k++)
        acc += Fs[r][k] * Ws[f][k];

    g_h[(size_t)(i0 + r) * OUT_F + f] = acc;

    float t1 = acc * a[f];
    float t2 = acc * a[OUT_F + f];
#pragma unroll
    for (int off = 16; off; off >>= 1) {
        t1 += __shfl_xor_sync(0xffffffffu, t1, off);
        t2 += __shfl_xor_sync(0xffffffffu, t2, off);
    }
    int w = tid >> 5;  // warp w covers f-range [0,31] or [32,63] of row w/2
    if ((tid & 31) == 0) { red1[w] = t1; red2[w] = t2; }
    __syncthreads();
    if (tid < 16) {
        g_s1[i0 + tid] = red1[2 * tid] + red1[2 * tid + 1];
        g_s2[i0 + tid] = red2[2 * tid] + red2[2 * tid + 1];
    }
}

// ---------------------------------------------------------------------------
// Kernel B: g_M = max_j s2[j]
// ---------------------------------------------------------------------------
__global__ __launch_bounds__(256) void k_max() {
    __shared__ float red[8];
    int tid = threadIdx.x;
    float m = -1e30f;
    for (int i = tid; i < NN; i += 256) m = fmaxf(m, g_s2[i]);
#pragma unroll
    for (int off = 16; off; off >>= 1)
        m = fmaxf(m, __shfl_xor_sync(0xffffffffu, m, off));
    if ((tid & 31) == 0) red[tid >> 5] = m;
    __syncthreads();
    if (tid == 0) {
        float mm = red[0];
#pragma unroll
        for (int i = 1; i < 8; i++) mm = fmaxf(mm, red[i]);
        g_M = mm;
    }
}

// ---------------------------------------------------------------------------
// Kernel C: fused score + bound-shifted softmax + P@h + ELU.
// Block = 64 rows, 256 threads, j chunks of 32, one streaming pass over adj.
//   Stage 1 (thread (w = tid/32, lane)): p[w*8+k][lane] for k=0..7,
//           coalesced adj loads prefetched one chunk ahead.
//   Stage 2 (thread (rt = tid/16, ct = tid%16)): 4x4 micro-tile fp32 matmul.
// ---------------------------------------------------------------------------
__global__ __launch_bounds__(256) void k_main(const float* __restrict__ geo,
                                              const float* __restrict__ sem,
                                              float* __restrict__ out) {
    __shared__ float Ps[64][33];    // p tile, +1 pad row pitch -> conflict-free STS
    __shared__ float Hs[32][OUT_F]; // h chunk
    __shared__ float S1s[64];
    __shared__ float Bs[64];
    __shared__ float Ds[64];

    int tid = threadIdx.x;
    int i0  = blockIdx.x * 64;

    if (tid < 64) {
        float s1 = g_s1[i0 + tid];
        S1s[tid] = s1;
        Bs[tid]  = fmaxf(0.f, 2.f * (s1 + g_M));  // upper bound on any score in row
    }

    int lane  = tid & 31;
    int w     = tid >> 5;       // 0..7
    int rbase = w * 8;          // rows handled by this warp in stage 1

    float dloc[8];
#pragma unroll
    for (int k = 0; k < 8; k++) dloc[k] = 0.f;

    int ct = tid & 15, rt = tid >> 4;
    int f0 = ct * 4, r0 = rt * 4;
    float acc[4][4];
#pragma unroll
    for (int i = 0; i < 4; i++)
#pragma unroll
        for (int j = 0; j < 4; j++) acc[i][j] = 0.f;

    __syncthreads();

    // Prefetch chunk 0 (adjacency + column scores) into registers
    float gv[8], sv[8], s2v;
    {
        size_t base = (size_t)(i0 + rbase) * NN + lane;
#pragma unroll
        for (int k = 0; k < 8; k++) {
            gv[k] = geo[base + (size_t)k * NN];
            sv[k] = sem[base + (size_t)k * NN];
        }
        s2v = g_s2[lane];
    }

    const int NC = NN / 32;
    for (int c = 0; c < NC; ++c) {
        int j0 = c * 32;

        // Load h chunk into registers (L2-resident, 2 MB total)
        float4 hv0 = *(const float4*)&g_h[(size_t)(j0 + (tid >> 4)) * OUT_F + (tid & 15) * 4];
        int t1i = tid + 256;
        float4 hv1 = *(const float4*)&g_h[(size_t)(j0 + (t1i >> 4)) * OUT_F + (t1i & 15) * 4];

        // Stage 1: p = masked exp(leaky(x)*c - B)
#pragma unroll
        for (int k = 0; k < 8; k++) {
            float cmb = gv[k] + sv[k];
            float x   = S1s[rbase + k] + s2v;
            float e   = (x > 0.f ? x : ALPHA * x) * cmb;
            float p   = (cmb > 0.f) ? __expf(e - Bs[rbase + k]) : 0.f;
            dloc[k]  += p;
            Ps[rbase + k][lane] = p;
        }
        *(float4*)&Hs[tid >> 4][(tid & 15) * 4] = hv0;
        *(float4*)&Hs[t1i >> 4][(t1i & 15) * 4] = hv1;
        __syncthreads();

        // Prefetch next chunk's adj (latency hidden behind the matmul below)
        {
            int jn = (c + 1 < NC) ? (j0 + 32) : 0;
            size_t base = (size_t)(i0 + rbase) * NN + jn + lane;
#pragma unroll
            for (int k = 0; k < 8; k++) {
                gv[k] = geo[base + (size_t)k * NN];
                sv[k] = sem[base + (size_t)k * NN];
            }
            s2v = g_s2[jn + lane];
        }

        // Stage 2: acc[64x64] += Ps[64x32] @ Hs[32x64], 4x4 per-thread tiles
#pragma unroll
        for (int jj = 0; jj < 32; jj++) {
            float4 hvv = *(const float4*)&Hs[jj][f0];
            float p0 = Ps[r0 + 0][jj];
            float p1 = Ps[r0 + 1][jj];
            float p2 = Ps[r0 + 2][jj];
            float p3 = Ps[r0 + 3][jj];
            acc[0][0] += p0 * hvv.x; acc[0][1] += p0 * hvv.y; acc[0][2] += p0 * hvv.z; acc[0][3] += p0 * hvv.w;
            acc[1][0] += p1 * hvv.x; acc[1][1] += p1 * hvv.y; acc[1][2] += p1 * hvv.z; acc[1][3] += p1 * hvv.w;
            acc[2][0] += p2 * hvv.x; acc[2][1] += p2 * hvv.y; acc[2][2] += p2 * hvv.z; acc[2][3] += p2 * hvv.w;
            acc[3][0] += p3 * hvv.x; acc[3][1] += p3 * hvv.y; acc[3][2] += p3 * hvv.z; acc[3][3] += p3 * hvv.w;
        }
        __syncthreads();
    }

    // Row denominators: reduce each warp's 8 row partials across 32 lanes
#pragma unroll
    for (int k = 0; k < 8; k++) {
        float v = dloc[k];
#pragma unroll
        for (int off = 16; off; off >>= 1)
            v += __shfl_xor_sync(0xffffffffu, v, off);
        if (lane == 0) Ds[rbase + k] = v;
    }
    __syncthreads();

    // Normalize + ELU + store
#pragma unroll
    for (int i = 0; i < 4; i++) {
        float inv = 1.0f / Ds[r0 + i];
        float4 o;
        float v;
        v = acc[i][0] * inv; o.x = (v > 0.f) ? v : expm1f(v);
        v = acc[i][1] * inv; o.y = (v > 0.f) ? v : expm1f(v);
        v = acc[i][2] * inv; o.z = (v > 0.f) ? v : expm1f(v);
        v = acc[i][3] * inv; o.w = (v > 0.f) ? v : expm1f(v);
        *(float4*)&out[(size_t)(i0 + r0 + i) * OUT_F + f0] = o;
    }
}

// ---------------------------------------------------------------------------
extern "C" void kernel_launch(void* const* d_in, const int* in_sizes, int n_in,
                              void* d_out, int out_size) {
    const float* geo  = (const float*)d_in[0];
    const float* sem  = (const float*)d_in[1];
    const float* feat = (const float*)d_in[2];
    const float* W    = (const float*)d_in[3];
    const float* a    = (const float*)d_in[4];
    float* out = (float*)d_out;

    k_proj<<<NN / 16, 1024>>>(feat, W, a);
    k_max<<<1, 256>>>();
    k_main<<<NN / 64, 256>>>(geo, sem, out);
}

// round 4
// speedup vs baseline: 2.1441x; 2.1441x over previous
#include <cuda_runtime.h>
#include <cuda_fp16.h>
#include <cstdint>
#include <math.h>

#define NN 8192
#define IN_F 128
#define OUT_F 64
#define ALPHA 0.2f
#define NCH 128          // chunks of 32 cols over a 4096-col half

// ---------------- device scratch (allocation-free rule) ----------------
__device__ float  g_s1[NN];
__device__ float  g_s2[NN];
__device__ float  g_M;
__device__ __half g_hT[(size_t)OUT_F * NN];     // H^T fp16, [f][j]
__device__ float  g_num[(size_t)2 * NN * OUT_F];
__device__ float  g_den[2 * NN];

// ---------------------------------------------------------------------------
// Kernel A: h = feat @ W^T ; s1/s2 row scores ; g_hT = fp16(h)^T
// ---------------------------------------------------------------------------
__global__ __launch_bounds__(1024) void k_proj(const float* __restrict__ feat,
                                               const float* __restrict__ W,
                                               const float* __restrict__ a) {
    __shared__ float Ws[OUT_F][IN_F + 4];   // +4 pad keeps float4 alignment
    __shared__ float Fs[16][IN_F];
    __shared__ float red1[32], red2[32];
    __shared__ __half Ts[OUT_F][18];

    int tid = threadIdx.x;
    int i0  = blockIdx.x * 16;

    for (int t = tid; t < OUT_F * IN_F; t += 1024)
        Ws[t / IN_F][t % IN_F] = W[t];
    for (int t = tid; t < 16 * IN_F; t += 1024)
        Fs[t / IN_F][t % IN_F] = feat[(size_t)(i0 + t / IN_F) * IN_F + (t % IN_F)];
    __syncthreads();

    int f = tid & 63;
    int r = tid >> 6;
    float acc = 0.f;
#pragma unroll
    for (int k = 0; k < IN_F; k += 4) {
        float4 fv = *(const float4*)&Fs[r][k];
        float4 wv = *(const float4*)&Ws[f][k];
        acc += fv.x * wv.x + fv.y * wv.y + fv.z * wv.z + fv.w * wv.w;
    }

    Ts[f][r] = __float2half(acc);

    float t1 = acc * a[f];
    float t2 = acc * a[OUT_F + f];
#pragma unroll
    for (int off = 16; off; off >>= 1) {
        t1 += __shfl_xor_sync(0xffffffffu, t1, off);
        t2 += __shfl_xor_sync(0xffffffffu, t2, off);
    }
    int w = tid >> 5;
    if ((tid & 31) == 0) { red1[w] = t1; red2[w] = t2; }
    __syncthreads();
    if (tid < 16) {
        g_s1[i0 + tid] = red1[2 * tid] + red1[2 * tid + 1];
        g_s2[i0 + tid] = red2[2 * tid] + red2[2 * tid + 1];
    }
    if (tid < 512) {
        int ff = tid >> 3, u = tid & 7;
        __half2 pk = __halves2half2(Ts[ff][2 * u], Ts[ff][2 * u + 1]);
        *(__half2*)&g_hT[(size_t)ff * NN + i0 + 2 * u] = pk;
    }
}

// ---------------------------------------------------------------------------
// Kernel B: g_M = max_j s2[j]
// ---------------------------------------------------------------------------
__global__ __launch_bounds__(256) void k_max() {
    __shared__ float red[8];
    int tid = threadIdx.x;
    float m = -1e30f;
    for (int i = tid; i < NN; i += 256) m = fmaxf(m, g_s2[i]);
#pragma unroll
    for (int off = 16; off; off >>= 1)
        m = fmaxf(m, __shfl_xor_sync(0xffffffffu, m, off));
    if ((tid & 31) == 0) red[tid >> 5] = m;
    __syncthreads();
    if (tid == 0) {
        float mm = red[0];
#pragma unroll
        for (int i = 1; i < 8; i++) mm = fmaxf(mm, red[i]);
        g_M = mm;
    }
}

// ---------------------------------------------------------------------------
// Main fused kernel: 128 CTAs = 64 row-tiles(128 rows) x 2 K-halves.
// 8 warps x 16 rows; chunks of 32 cols; P computed in mma A-frag layout,
// H^T chunk staged to SMEM, B-frags via ldmatrix.x4, mma.sync m16n8k16 fp16.
// ---------------------------------------------------------------------------
struct AdjRegs {
    float2 G[2][2][2];   // [row(r / r+8)][kk][chalf]
    float2 S[2][2][2];
    float2 Z[2][2];      // s2 [kk][chalf]
    uint4  Bv;           // H^T staging fragment (this thread's 16B)
};

__device__ __forceinline__ void load_chunk(const float* __restrict__ gp0,
                                           const float* __restrict__ sp0,
                                           const float* __restrict__ s2p,
                                           const __half* __restrict__ bp,
                                           int c, AdjRegs& A) {
    size_t off = (size_t)c * 32;
#pragma unroll
    for (int ro = 0; ro < 2; ro++)
#pragma unroll
        for (int kk = 0; kk < 2; kk++)
#pragma unroll
            for (int ch = 0; ch < 2; ch++) {
                size_t o = off + (size_t)ro * 8 * NN + kk * 16 + ch * 8;
                A.G[ro][kk][ch] = *(const float2*)(gp0 + o);
                A.S[ro][kk][ch] = *(const float2*)(sp0 + o);
            }
#pragma unroll
    for (int kk = 0; kk < 2; kk++)
#pragma unroll
        for (int ch = 0; ch < 2; ch++)
            A.Z[kk][ch] = *(const float2*)(s2p + off + kk * 16 + ch * 8);
    A.Bv = *(const uint4*)(bp + off);
}

__device__ __forceinline__ void mma16816(float* d, const uint32_t* a,
                                         uint32_t b0, uint32_t b1) {
    asm volatile(
        "mma.sync.aligned.m16n8k16.row.col.f32.f16.f16.f32 "
        "{%0,%1,%2,%3},{%4,%5,%6,%7},{%8,%9},{%0,%1,%2,%3};"
        : "+f"(d[0]), "+f"(d[1]), "+f"(d[2]), "+f"(d[3])
        : "r"(a[0]), "r"(a[1]), "r"(a[2]), "r"(a[3]), "r"(b0), "r"(b1));
}

__device__ __forceinline__ void proc_chunk(int c, AdjRegs& cur, AdjRegs& nxt,
                                           char* buf,
                                           const float* gp0, const float* sp0,
                                           const float* s2p, const __half* bp,
                                           int fstage, int seg, uint32_t ldbase,
                                           float s10, float s11, float bn0, float bn1,
                                           float (&dloc)[2], float (&acc)[8][4]) {
    // 1. stage this chunk's H^T tile into smem
    *(uint4*)(buf + fstage * 80 + seg * 16) = cur.Bv;

    // 2. prefetch next chunk (in-flight across the whole mma section)
    int cn = (c + 1 < NCH) ? c + 1 : 0;
    load_chunk(gp0, sp0, s2p, bp, cn, nxt);

    // 3. compute P in A-fragment layout
    uint32_t af[2][4];
#pragma unroll
    for (int kk = 0; kk < 2; kk++)
#pragma unroll
        for (int ch = 0; ch < 2; ch++)
#pragma unroll
            for (int ro = 0; ro < 2; ro++) {
                float2 g = cur.G[ro][kk][ch], s = cur.S[ro][kk][ch];
                float cmx = g.x + s.x, cmy = g.y + s.y;
                float s1 = ro ? s11 : s10;
                float bn = ro ? bn1 : bn0;
                float xx = s1 + cur.Z[kk][ch].x;
                float xy = s1 + cur.Z[kk][ch].y;
                float lx = (xx > 0.f ? xx : ALPHA * xx);
                float ly = (xy > 0.f ? xy : ALPHA * xy);
                float px = (cmx > 0.f) ? __expf(lx * cmx - bn) : 0.f;
                float py = (cmy > 0.f) ? __expf(ly * cmy - bn) : 0.f;
                __half2 ph = __floats2half2_rn(px, py);
                float2 pf = __half22float2(ph);    // rounded: num/den consistent
                dloc[ro] += pf.x + pf.y;
                af[kk][ro + 2 * ch] = *(uint32_t*)&ph;
            }

    __syncthreads();   // STS of all threads visible

    // 4. B-frags via ldmatrix, 16 mma
#pragma unroll
    for (int kk = 0; kk < 2; kk++) {
#pragma unroll
        for (int t = 0; t < 4; t++) {
            uint32_t b0, b1, b2, b3;
            uint32_t ad = ldbase + t * (16 * 80) + kk * 32;
            asm volatile(
                "ldmatrix.sync.aligned.m8n8.x4.shared.b16 {%0,%1,%2,%3}, [%4];"
                : "=r"(b0), "=r"(b1), "=r"(b2), "=r"(b3) : "r"(ad));
            mma16816(acc[2 * t],     af[kk], b0, b1);
            mma16816(acc[2 * t + 1], af[kk], b2, b3);
        }
    }
}

__global__ __launch_bounds__(256, 1) void k_main(const float* __restrict__ geo,
                                                 const float* __restrict__ sem) {
    __shared__ __align__(16) char Bbuf[2][64 * 80];   // H^T chunk, 80B row pitch

    int tid = threadIdx.x, lane = tid & 31, w = tid >> 5;
    int r = lane >> 2, tg = lane & 3;
    int rb = blockIdx.x >> 1, half = blockIdx.x & 1;
    int i0 = rb * 128, jbase = half * 4096;

    int row0 = i0 + 16 * w + r;
    const float* gp0 = geo + (size_t)row0 * NN + jbase + 2 * tg;
    const float* sp0 = sem + (size_t)row0 * NN + jbase + 2 * tg;
    const float* s2p = g_s2 + jbase + 2 * tg;
    int fstage = tid >> 2, seg = tid & 3;
    const __half* bp = g_hT + (size_t)fstage * NN + jbase + seg * 8;

    float Mv  = g_M;
    float s10 = g_s1[row0], s11 = g_s1[row0 + 8];
    float bn0 = fmaxf(0.f, 2.f * (s10 + Mv));
    float bn1 = fmaxf(0.f, 2.f * (s11 + Mv));

    // ldmatrix per-lane address (quad mapping for x4)
    int ldrow = ((lane >> 4) & 1) * 8 + (lane & 7);
    int ldcol = ((lane >> 3) & 1) * 16;

    uint32_t smem0;
    asm("{ .reg .u64 t; cvta.to.shared.u64 t, %1; cvt.u32.u64 %0, t; }"
        : "=r"(smem0) : "l"(&Bbuf[0][0]));
    uint32_t ldb0 = smem0 + ldrow * 80 + ldcol;
    uint32_t ldb1 = ldb0 + 64 * 80;

    float acc[8][4];
#pragma unroll
    for (int i = 0; i < 8; i++)
#pragma unroll
        for (int j = 0; j < 4; j++) acc[i][j] = 0.f;
    float dloc[2] = {0.f, 0.f};

    AdjRegs A0, A1;
    load_chunk(gp0, sp0, s2p, bp, 0, A0);

    for (int c = 0; c < NCH; c += 2) {
        proc_chunk(c,     A0, A1, Bbuf[0], gp0, sp0, s2p, bp,
                   fstage, seg, ldb0, s10, s11, bn0, bn1, dloc, acc);
        proc_chunk(c + 1, A1, A0, Bbuf[1], gp0, sp0, s2p, bp,
                   fstage, seg, ldb1, s10, s11, bn0, bn1, dloc, acc);
    }

    // denominators: reduce over the 4 lanes of each row-quad
#pragma unroll
    for (int ro = 0; ro < 2; ro++) {
        float v = dloc[ro];
        v += __shfl_xor_sync(0xffffffffu, v, 1);
        v += __shfl_xor_sync(0xffffffffu, v, 2);
        dloc[ro] = v;
    }
    if (tg == 0) {
        g_den[half * NN + row0]     = dloc[0];
        g_den[half * NN + row0 + 8] = dloc[1];
    }

    // numerator partials: c-frag layout -> float2 stores
    float* dst0 = g_num + ((size_t)half * NN + row0) * OUT_F;
    float* dst1 = g_num + ((size_t)half * NN + row0 + 8) * OUT_F;
#pragma unroll
    for (int t = 0; t < 8; t++) {
        int n0 = 8 * t + 2 * tg;
        *(float2*)(dst0 + n0) = make_float2(acc[t][0], acc[t][1]);
        *(float2*)(dst1 + n0) = make_float2(acc[t][2], acc[t][3]);
    }
}

// ---------------------------------------------------------------------------
// Combine split-K partials: out = elu((n0+n1)/(d0+d1))
// ---------------------------------------------------------------------------
__global__ __launch_bounds__(256) void k_fin(float* __restrict__ out) {
    int idx = blockIdx.x * 256 + threadIdx.x;
    int row = idx >> 4, q = idx & 15;
    float inv = 1.0f / (g_den[row] + g_den[NN + row]);
    float4 n0 = *(const float4*)&g_num[(size_t)row * OUT_F + 4 * q];
    float4 n1 = *(const float4*)&g_num[(size_t)(NN + row) * OUT_F + 4 * q];
    float4 o;
    float v;
    v = (n0.x + n1.x) * inv; o.x = (v > 0.f) ? v : expm1f(v);
    v = (n0.y + n1.y) * inv; o.y = (v > 0.f) ? v : expm1f(v);
    v = (n0.z + n1.z) * inv; o.z = (v > 0.f) ? v : expm1f(v);
    v = (n0.w + n1.w) * inv; o.w = (v > 0.f) ? v : expm1f(v);
    *(float4*)&out[(size_t)row * OUT_F + 4 * q] = o;
}

// ---------------------------------------------------------------------------
extern "C" void kernel_launch(void* const* d_in, const int* in_sizes, int n_in,
                              void* d_out, int out_size) {
    const float* geo  = (const float*)d_in[0];
    const float* sem  = (const float*)d_in[1];
    const float* feat = (const float*)d_in[2];
    const float* W    = (const float*)d_in[3];
    const float* a    = (const float*)d_in[4];
    float* out = (float*)d_out;

    k_proj<<<NN / 16, 1024>>>(feat, W, a);
    k_max<<<1, 256>>>();
    k_main<<<128, 256>>>(geo, sem);
    k_fin<<<512, 256>>>(out);
}

// round 5
// speedup vs baseline: 2.6695x; 1.2450x over previous
#include <cuda_runtime.h>
#include <cuda_fp16.h>
#include <cstdint>
#include <math.h>

#define NN 8192
#define IN_F 128
#define OUT_F 64
#define ALPHA 0.2f
#define NCH 128          // chunks of 32 cols over a 4096-col half
#define SBCH 16          // chunks per superblock (512 cols)
#define BPITCH 1040      // smem row pitch: 1040/16=65 -> aligned; bank-rotates by 4
#define BBYTES (64 * BPITCH)

// ---------------- device scratch (allocation-free rule) ----------------
__device__ float  g_s1[NN];
__device__ float  g_s2[NN];
__device__ float  g_M;
__device__ __half g_hT[(size_t)OUT_F * NN];     // H^T fp16, [f][j]
__device__ float  g_num[(size_t)2 * NN * OUT_F];
__device__ float  g_den[2 * NN];

// ---------------------------------------------------------------------------
// Kernel A: h = feat @ W^T ; s1/s2 row scores ; g_hT = fp16(h)^T
// ---------------------------------------------------------------------------
__global__ __launch_bounds__(1024) void k_proj(const float* __restrict__ feat,
                                               const float* __restrict__ W,
                                               const float* __restrict__ a) {
    __shared__ float Ws[OUT_F][IN_F + 4];
    __shared__ float Fs[16][IN_F];
    __shared__ float red1[32], red2[32];
    __shared__ __half Ts[OUT_F][18];

    int tid = threadIdx.x;
    int i0  = blockIdx.x * 16;

    for (int t = tid; t < OUT_F * IN_F; t += 1024)
        Ws[t / IN_F][t % IN_F] = W[t];
    for (int t = tid; t < 16 * IN_F; t += 1024)
        Fs[t / IN_F][t % IN_F] = feat[(size_t)(i0 + t / IN_F) * IN_F + (t % IN_F)];
    __syncthreads();

    int f = tid & 63;
    int r = tid >> 6;
    float acc = 0.f;
#pragma unroll
    for (int k = 0; k < IN_F; k += 4) {
        float4 fv = *(const float4*)&Fs[r][k];
        float4 wv = *(const float4*)&Ws[f][k];
        acc += fv.x * wv.x + fv.y * wv.y + fv.z * wv.z + fv.w * wv.w;
    }

    Ts[f][r] = __float2half(acc);

    float t1 = acc * a[f];
    float t2 = acc * a[OUT_F + f];
#pragma unroll
    for (int off = 16; off; off >>= 1) {
        t1 += __shfl_xor_sync(0xffffffffu, t1, off);
        t2 += __shfl_xor_sync(0xffffffffu, t2, off);
    }
    int w = tid >> 5;
    if ((tid & 31) == 0) { red1[w] = t1; red2[w] = t2; }
    __syncthreads();
    if (tid < 16) {
        g_s1[i0 + tid] = red1[2 * tid] + red1[2 * tid + 1];
        g_s2[i0 + tid] = red2[2 * tid] + red2[2 * tid + 1];
    }
    if (tid < 512) {
        int ff = tid >> 3, u = tid & 7;
        __half2 pk = __halves2half2(Ts[ff][2 * u], Ts[ff][2 * u + 1]);
        *(__half2*)&g_hT[(size_t)ff * NN + i0 + 2 * u] = pk;
    }
}

// ---------------------------------------------------------------------------
// Kernel B: g_M = max_j s2[j]
// ---------------------------------------------------------------------------
__global__ __launch_bounds__(256) void k_max() {
    __shared__ float red[8];
    int tid = threadIdx.x;
    float m = -1e30f;
    for (int i = tid; i < NN; i += 256) m = fmaxf(m, g_s2[i]);
#pragma unroll
    for (int off = 16; off; off >>= 1)
        m = fmaxf(m, __shfl_xor_sync(0xffffffffu, m, off));
    if ((tid & 31) == 0) red[tid >> 5] = m;
    __syncthreads();
    if (tid == 0) {
        float mm = red[0];
#pragma unroll
        for (int i = 1; i < 8; i++) mm = fmaxf(mm, red[i]);
        g_M = mm;
    }
}

// ---------------------------------------------------------------------------
// Main fused kernel. 128 CTAs = 64 row-tiles(128 rows) x 2 K-halves.
// H^T staged in 512-col superblocks via cp.async; ONE __syncthreads per 16
// chunks -> warps run chunks independently (exp overlaps HMMA across warps).
// ---------------------------------------------------------------------------
struct AdjRegs {
    float2 G[2][2][2];   // [row(r / r+8)][kk][chalf]
    float2 S[2][2][2];
    float2 Z[2][2];      // s2 [kk][chalf]
};

__device__ __forceinline__ void load_chunk(const float* __restrict__ gp0,
                                           const float* __restrict__ sp0,
                                           const float* __restrict__ s2p,
                                           int c, AdjRegs& A) {
    size_t off = (size_t)c * 32;
#pragma unroll
    for (int ro = 0; ro < 2; ro++)
#pragma unroll
        for (int kk = 0; kk < 2; kk++)
#pragma unroll
            for (int ch = 0; ch < 2; ch++) {
                size_t o = off + (size_t)ro * 8 * NN + kk * 16 + ch * 8;
                A.G[ro][kk][ch] = __ldcs((const float2*)(gp0 + o));
                A.S[ro][kk][ch] = __ldcs((const float2*)(sp0 + o));
            }
#pragma unroll
    for (int kk = 0; kk < 2; kk++)
#pragma unroll
        for (int ch = 0; ch < 2; ch++)
            A.Z[kk][ch] = *(const float2*)(s2p + off + kk * 16 + ch * 8);
}

__device__ __forceinline__ void mma16816(float* d, const uint32_t* a,
                                         uint32_t b0, uint32_t b1) {
    asm volatile(
        "mma.sync.aligned.m16n8k16.row.col.f32.f16.f16.f32 "
        "{%0,%1,%2,%3},{%4,%5,%6,%7},{%8,%9},{%0,%1,%2,%3};"
        : "+f"(d[0]), "+f"(d[1]), "+f"(d[2]), "+f"(d[3])
        : "r"(a[0]), "r"(a[1]), "r"(a[2]), "r"(a[3]), "r"(b0), "r"(b1));
}

__device__ __forceinline__ void proc_chunk(int c, AdjRegs& cur, AdjRegs& nxt,
                                           const float* gp0, const float* sp0,
                                           const float* s2p, uint32_t ldb,
                                           float s10, float s11, float bn0, float bn1,
                                           float (&dloc)[2], float (&acc)[8][4]) {
    // 1. prefetch next chunk's adjacency (in flight across whole chunk)
    int cn = (c + 1 < NCH) ? c + 1 : 0;
    load_chunk(gp0, sp0, s2p, cn, nxt);

    // 2. compute P in A-fragment layout
    uint32_t af[2][4];
#pragma unroll
    for (int kk = 0; kk < 2; kk++)
#pragma unroll
        for (int ch = 0; ch < 2; ch++)
#pragma unroll
            for (int ro = 0; ro < 2; ro++) {
                float2 g = cur.G[ro][kk][ch], s = cur.S[ro][kk][ch];
                float cmx = g.x + s.x, cmy = g.y + s.y;
                float s1 = ro ? s11 : s10;
                float bn = ro ? bn1 : bn0;
                float xx = s1 + cur.Z[kk][ch].x;
                float xy = s1 + cur.Z[kk][ch].y;
                float lx = (xx > 0.f ? xx : ALPHA * xx);
                float ly = (xy > 0.f ? xy : ALPHA * xy);
                float px = (cmx > 0.f) ? __expf(lx * cmx - bn) : 0.f;
                float py = (cmy > 0.f) ? __expf(ly * cmy - bn) : 0.f;
                __half2 ph = __floats2half2_rn(px, py);
                float2 pf = __half22float2(ph);    // rounded: num/den consistent
                dloc[ro] += pf.x + pf.y;
                af[kk][ro + 2 * ch] = *(uint32_t*)&ph;
            }

    // 3. B-frags from the superblock buffer (no sync needed), 16 mma
    uint32_t base = ldb + (uint32_t)(c & (SBCH - 1)) * 64;
#pragma unroll
    for (int kk = 0; kk < 2; kk++) {
#pragma unroll
        for (int t = 0; t < 4; t++) {
            uint32_t b0, b1, b2, b3;
            uint32_t ad = base + t * (16 * BPITCH) + kk * 32;
            asm volatile(
                "ldmatrix.sync.aligned.m8n8.x4.shared.b16 {%0,%1,%2,%3}, [%4];"
                : "=r"(b0), "=r"(b1), "=r"(b2), "=r"(b3) : "r"(ad));
            mma16816(acc[2 * t],     af[kk], b0, b1);
            mma16816(acc[2 * t + 1], af[kk], b2, b3);
        }
    }
}

__global__ __launch_bounds__(256, 1) void k_main(const float* __restrict__ geo,
                                                 const float* __restrict__ sem) {
    extern __shared__ __align__(16) char Bbuf[];   // 2 x 64 rows x 1040B

    int tid = threadIdx.x, lane = tid & 31, w = tid >> 5;
    int r = lane >> 2, tg = lane & 3;
    int rb = blockIdx.x >> 1, half = blockIdx.x & 1;
    int i0 = rb * 128, jbase = half * 4096;

    int row0 = i0 + 16 * w + r;
    const float* gp0 = geo + (size_t)row0 * NN + jbase + 2 * tg;
    const float* sp0 = sem + (size_t)row0 * NN + jbase + 2 * tg;
    const float* s2p = g_s2 + jbase + 2 * tg;

    float Mv  = g_M;
    float s10 = g_s1[row0], s11 = g_s1[row0 + 8];
    float bn0 = fmaxf(0.f, 2.f * (s10 + Mv));
    float bn1 = fmaxf(0.f, 2.f * (s11 + Mv));

    uint32_t smem0;
    asm("{ .reg .u64 t; cvta.to.shared.u64 t, %1; cvt.u32.u64 %0, t; }"
        : "=r"(smem0) : "l"(Bbuf));

    // cp.async staging map: thread covers (f = tid>>6 + 4p, j = (tid&63)*8)
    int sf = tid >> 6, sj = tid & 63;
    const __half* gsrc0 = g_hT + (size_t)sf * NN + jbase + sj * 8;
    uint32_t sdst0 = smem0 + sf * BPITCH + sj * 16;

    // ldmatrix per-lane base
    int ldrow = ((lane >> 4) & 1) * 8 + (lane & 7);
    int ldcol = ((lane >> 3) & 1) * 16;
    uint32_t ldb0 = smem0 + ldrow * BPITCH + ldcol;

    float acc[8][4];
#pragma unroll
    for (int i = 0; i < 8; i++)
#pragma unroll
        for (int j = 0; j < 4; j++) acc[i][j] = 0.f;
    float dloc[2] = {0.f, 0.f};

    // prologue: stage superblock 0
#pragma unroll
    for (int p = 0; p < 16; p++) {
        const __half* gp = gsrc0 + (size_t)(4 * p) * NN;
        uint32_t sd = sdst0 + 4 * p * BPITCH;
        asm volatile("cp.async.cg.shared.global [%0], [%1], 16;" :: "r"(sd), "l"(gp));
    }
    asm volatile("cp.async.commit_group;");
    asm volatile("cp.async.wait_group 0;");

    AdjRegs A0, A1;
    load_chunk(gp0, sp0, s2p, 0, A0);
    __syncthreads();

    int c = 0;
    for (int sb = 0; sb < NCH / SBCH; sb++) {
        // stage next superblock into the other buffer
        if (sb + 1 < NCH / SBCH) {
            int jblk = (sb + 1) * (SBCH * 32);
            uint32_t sd0 = sdst0 + ((sb + 1) & 1) * BBYTES;
#pragma unroll
            for (int p = 0; p < 16; p++) {
                const __half* gp = gsrc0 + (size_t)(4 * p) * NN + jblk;
                asm volatile("cp.async.cg.shared.global [%0], [%1], 16;"
                             :: "r"(sd0 + 4 * p * BPITCH), "l"(gp));
            }
            asm volatile("cp.async.commit_group;");
        }

        uint32_t ldb = ldb0 + (sb & 1) * BBYTES;
#pragma unroll 2
        for (int cc = 0; cc < SBCH; cc += 2) {
            proc_chunk(c,     A0, A1, gp0, sp0, s2p, ldb, s10, s11, bn0, bn1, dloc, acc);
            proc_chunk(c + 1, A1, A0, gp0, sp0, s2p, ldb, s10, s11, bn0, bn1, dloc, acc);
            c += 2;
        }

        asm volatile("cp.async.wait_group 0;");
        __syncthreads();
    }

    // denominators: reduce over the 4 lanes of each row-quad
#pragma unroll
    for (int ro = 0; ro < 2; ro++) {
        float v = dloc[ro];
        v += __shfl_xor_sync(0xffffffffu, v, 1);
        v += __shfl_xor_sync(0xffffffffu, v, 2);
        dloc[ro] = v;
    }
    if (tg == 0) {
        g_den[half * NN + row0]     = dloc[0];
        g_den[half * NN + row0 + 8] = dloc[1];
    }

    // numerator partials: c-frag layout -> float2 stores
    float* dst0 = g_num + ((size_t)half * NN + row0) * OUT_F;
    float* dst1 = g_num + ((size_t)half * NN + row0 + 8) * OUT_F;
#pragma unroll
    for (int t = 0; t < 8; t++) {
        int n0 = 8 * t + 2 * tg;
        *(float2*)(dst0 + n0) = make_float2(acc[t][0], acc[t][1]);
        *(float2*)(dst1 + n0) = make_float2(acc[t][2], acc[t][3]);
    }
}

// ---------------------------------------------------------------------------
// Combine split-K partials: out = elu((n0+n1)/(d0+d1))
// ---------------------------------------------------------------------------
__global__ __launch_bounds__(256) void k_fin(float* __restrict__ out) {
    int idx = blockIdx.x * 256 + threadIdx.x;
    int row = idx >> 4, q = idx & 15;
    float inv = 1.0f / (g_den[row] + g_den[NN + row]);
    float4 n0 = *(const float4*)&g_num[(size_t)row * OUT_F + 4 * q];
    float4 n1 = *(const float4*)&g_num[(size_t)(NN + row) * OUT_F + 4 * q];
    float4 o;
    float v;
    v = (n0.x + n1.x) * inv; o.x = (v > 0.f) ? v : expm1f(v);
    v = (n0.y + n1.y) * inv; o.y = (v > 0.f) ? v : expm1f(v);
    v = (n0.z + n1.z) * inv; o.z = (v > 0.f) ? v : expm1f(v);
    v = (n0.w + n1.w) * inv; o.w = (v > 0.f) ? v : expm1f(v);
    *(float4*)&out[(size_t)row * OUT_F + 4 * q] = o;
}

// ---------------------------------------------------------------------------
extern "C" void kernel_launch(void* const* d_in, const int* in_sizes, int n_in,
                              void* d_out, int out_size) {
    const float* geo  = (const float*)d_in[0];
    const float* sem  = (const float*)d_in[1];
    const float* feat = (const float*)d_in[2];
    const float* W    = (const float*)d_in[3];
    const float* a    = (const float*)d_in[4];
    float* out = (float*)d_out;

    const int DYN = 2 * BBYTES;   // 133,120 B
    cudaFuncSetAttribute(k_main, cudaFuncAttributeMaxDynamicSharedMemorySize, DYN);

    k_proj<<<NN / 16, 1024>>>(feat, W, a);
    k_max<<<1, 256>>>();
    k_main<<<128, 256, DYN>>>(geo, sem);
    k_fin<<<512, 256>>>(out);
}